// round 6
// baseline (speedup 1.0000x reference)
#include <cuda_runtime.h>

#define N_NODES 1000000
#define DEGREE 31
#define BLOCK 256
#define THRESH 16
#define GRID 888                        // 148 SMs x 6 CTAs (GB300 has 152 SMs)
#define WARP_TILES (N_NODES / 32)       // 31250, exact
#define WARPS_TOTAL (GRID * (BLOCK / 32))

__device__ float    g_p[N_NODES];
__device__ double   g_sum;
__device__ int      g_is64;
__device__ unsigned g_arrive = 0;
__device__ unsigned g_done   = 0;

// Two-sided pruned Poisson-binomial DP step block, trials [J0, J0+NV).
// dp[16] is absorbing P(>=16). State k after step j is useful only if
// k + (31 - j) >= 16  =>  k >= j - 15 (lower prune); k <= j+1 (upper prune).
template <int J0, int NV>
__device__ __forceinline__ void dp_run(float* __restrict__ dp,
                                       const float* __restrict__ v) {
    #pragma unroll
    for (int jj = 0; jj < NV; jj++) {
        const int j = J0 + jj;
        const float pj = v[jj];
        if (j >= THRESH - 1)
            dp[THRESH] = fmaf(pj, dp[THRESH - 1], dp[THRESH]);   // absorb
        const int khi = (j + 1 < THRESH) ? (j + 1) : (THRESH - 1);
        const int klo = (j - 15 > 1) ? (j - 15) : 1;
        #pragma unroll
        for (int k = THRESH - 1; k >= 1; k--)
            if (k <= khi && k >= klo)
                dp[k] = fmaf(pj, dp[k - 1] - dp[k], dp[k]);
        if (j <= 15)
            dp[0] = dp[0] * (1.0f - pj);
    }
}

__device__ __forceinline__ unsigned ld_acquire(const unsigned* p) {
    unsigned v;
    asm volatile("ld.acquire.gpu.u32 %0, [%1];" : "=r"(v) : "l"(p) : "memory");
    return v;
}

// Single fused persistent kernel:
//   Phase A: sigmoid table + dtype detection + accumulator zeroing.
//   Grid barrier (all 888 CTAs co-resident by __launch_bounds__(256,6)).
//   Phase B: warp-autonomous gather + DP over warp-tiles, no block barriers.
//   Final: block reduce, one double atomic per CTA, last CTA writes out.
__global__ void __launch_bounds__(BLOCK, 6)
fused_kernel(const float* __restrict__ gains,
             const void*  __restrict__ neighbors,
             float* __restrict__ out) {
    __shared__ int   sidx[BLOCK * DEGREE];   // per-warp slices of 32*DEGREE
    __shared__ float sred[BLOCK / 32];

    const int tid  = threadIdx.x;
    const int wid  = tid >> 5;
    const int lane = tid & 31;

    // ---- Phase A: p = sigmoid(gains), detection, zeroing ----
    if (blockIdx.x == 0 && tid < 32) {
        // int64 -> hi-words of first 32 elements are all 0 (indices < 2^20).
        // int32 -> those words are random indices in [0, 1e6): P(all 0) ~ 0.
        int hi = ((const int*)neighbors)[tid * 2 + 1];
        unsigned all0 = __ballot_sync(0xffffffffu, hi == 0);
        if (tid == 0) {
            g_is64 = (all0 == 0xffffffffu) ? 1 : 0;
            g_sum = 0.0;
        }
    }
    for (int i = blockIdx.x * BLOCK + tid; i < N_NODES; i += GRID * BLOCK) {
        float x = gains[i];
        g_p[i] = 1.0f / (1.0f + __expf(-x));
    }

    // ---- Grid barrier ----
    __threadfence();
    __syncthreads();
    if (tid == 0) {
        atomicAdd(&g_arrive, 1u);
        while (ld_acquire(&g_arrive) < (unsigned)gridDim.x) { }
    }
    __syncthreads();

    // ---- Phase B: warp-autonomous gather + DP ----
    const int is64 = g_is64;
    int* const sw = sidx + wid * (32 * DEGREE);
    float acc = 0.0f;

    for (int wt = blockIdx.x * (BLOCK / 32) + wid; wt < WARP_TILES;
         wt += WARPS_TOTAL) {
        const long long warpStart = (long long)wt * 32;
        const long long elemBase  = warpStart * (long long)DEGREE;

        // Stage this warp's 32x31 index rows, coalesced + vectorized.
        if (is64) {
            const int4* nb4 = (const int4*)((const long long*)neighbors + elemBase);
            #pragma unroll
            for (int t = lane; t < (32 * DEGREE) / 2; t += 32) {
                int4 v = nb4[t];
                sw[2 * t]     = v.x;
                sw[2 * t + 1] = v.z;
            }
        } else {
            const int4* nb4 = (const int4*)((const int*)neighbors + elemBase);
            #pragma unroll
            for (int t = lane; t < (32 * DEGREE) / 4; t += 32) {
                int4 v = nb4[t];
                sw[4 * t]     = v.x;
                sw[4 * t + 1] = v.y;
                sw[4 * t + 2] = v.z;
                sw[4 * t + 3] = v.w;
            }
        }
        __syncwarp();

        const int node = (int)(warpStart + lane);
        float pv[DEGREE + 1];
        pv[0] = g_p[node];
        #pragma unroll
        for (int j = 0; j < DEGREE; j++) {
            int idx = sw[lane * DEGREE + j];       // stride 31: conflict-free
            idx = min(max(idx, 0), N_NODES - 1);   // crash-proofing
            pv[j + 1] = __ldg(&g_p[idx]);
        }

        float dp[THRESH + 1];
        dp[0] = 1.0f;
        #pragma unroll
        for (int k = 1; k <= THRESH; k++) dp[k] = 0.0f;
        dp_run<0, DEGREE + 1>(dp, pv);

        acc += dp[THRESH] - 0.25f * pv[0];
        __syncwarp();   // guard sw reuse
    }

    // ---- Final reduction ----
    #pragma unroll
    for (int o = 16; o; o >>= 1)
        acc += __shfl_down_sync(0xffffffffu, acc, o);
    if (lane == 0) sred[wid] = acc;
    __syncthreads();
    if (tid < 32) {
        float v = (tid < BLOCK / 32) ? sred[tid] : 0.0f;
        #pragma unroll
        for (int o = 4; o; o >>= 1)
            v += __shfl_down_sync(0xffffffffu, v, o);
        if (tid == 0) {
            atomicAdd(&g_sum, (double)v);
            __threadfence();
            unsigned done = atomicAdd(&g_done, 1u);
            if (done == (unsigned)gridDim.x - 1u) {
                double s = atomicAdd(&g_sum, 0.0);   // L2-coherent read
                out[0] = -(float)s;
                g_done   = 0;                         // reset for graph replays
                g_arrive = 0;
            }
        }
    }
}

extern "C" void kernel_launch(void* const* d_in, const int* in_sizes, int n_in,
                              void* d_out, int out_size) {
    // Resolve input order from element counts (gains: 1M, neighbors: 31M).
    int gi = 0, ni = 1;
    if (in_sizes[0] != N_NODES) { gi = 1; ni = 0; }
    const float* gains     = (const float*)d_in[gi];
    const void*  neighbors = d_in[ni];
    float*       out       = (float*)d_out;

    fused_kernel<<<GRID, BLOCK>>>(gains, neighbors, out);
}